// round 2
// baseline (speedup 1.0000x reference)
#include <cuda_runtime.h>
#include <cuda_bf16.h>

#define NN 100000
#define NE 1200000
#define FEAT4 16           // 64 floats = 16 float4 per node
#define NCLS 40

// ---------------- device scratch (no allocs allowed) ----------------
__device__ int    g_src[NE];
__device__ int    g_dst[NE];
__device__ float  g_norm[NE];
__device__ float  g_deg[NN];
__device__ float  g_dinv[NN];
__device__ float4 g_hop1[NN * FEAT4];
__device__ float4 g_hop2[NN * FEAT4];
__device__ float4 g_hop3[NN * FEAT4];
__device__ float4 g_h1[NN * FEAT4];
__device__ float4 g_h2[NN * FEAT4];
__device__ int    g_is64;

// ---------------- dtype detection (int64 vs int32 edge_index) -------
// If the buffer is int32 pairs, an int64 read combines two random node ids
// (lo + hi*2^32): hi != 0 with overwhelming probability -> value >= NN.
// Sample indices i*997 (max 62811) stay inside the src half either way.
__global__ void k_detect(const long long* p) {
    if (blockIdx.x == 0 && threadIdx.x == 0) {
        int ok = 1;
        #pragma unroll 1
        for (int i = 0; i < 64; i++) {
            long long v = p[i * 997];
            if (v < 0 || v >= NN) { ok = 0; break; }
        }
        g_is64 = ok;
    }
}

__global__ void k_convert(const void* edges) {
    int e = blockIdx.x * blockDim.x + threadIdx.x;
    if (e >= NE) return;
    if (g_is64) {
        const long long* p = (const long long*)edges;
        g_src[e] = (int)p[e];
        g_dst[e] = (int)p[e + NE];
    } else {
        const int* p = (const int*)edges;
        g_src[e] = p[e];
        g_dst[e] = p[e + NE];
    }
}

// ---------------- gcn_norm (no self loops) --------------------------
__global__ void k_deg() {
    int e = blockIdx.x * blockDim.x + threadIdx.x;
    if (e < NE) atomicAdd(&g_deg[g_dst[e]], 1.0f);
}

__global__ void k_dinv() {
    int n = blockIdx.x * blockDim.x + threadIdx.x;
    if (n < NN) {
        float d = g_deg[n];
        g_dinv[n] = (d > 0.f) ? rsqrtf(fmaxf(d, 1.f)) : 0.f;
    }
}

__global__ void k_norm() {
    int e = blockIdx.x * blockDim.x + threadIdx.x;
    if (e < NE) g_norm[e] = g_dinv[g_src[e]] * g_dinv[g_dst[e]];
}

// ---------------- SpMM: out[dst] += norm * feat[src] ----------------
// 16 threads per edge, one float4 per thread, vector atomics (sm_90+).
__global__ void k_spmm(const float4* __restrict__ feat, float4* __restrict__ out) {
    int gid = blockIdx.x * blockDim.x + threadIdx.x;
    if (gid >= NE * FEAT4) return;
    int e = gid >> 4;
    int q = gid & 15;
    int s = g_src[e];
    int d = g_dst[e];
    float w = g_norm[e];
    float4 v = __ldg(&feat[s * FEAT4 + q]);
    float4 r = make_float4(v.x * w, v.y * w, v.z * w, v.w * w);
    atomicAdd(&out[d * FEAT4 + q], r);
}

// ---------------- GEMM: concat(4 x [N,64]) @ W[256,64] + b ----------
// Tile: 128 nodes x 64 cols per block, 128 threads, 8x8 register tile.
__global__ void __launch_bounds__(128) k_gemm(
    const float4* __restrict__ A0, const float4* __restrict__ A1,
    const float4* __restrict__ A2, const float4* __restrict__ A3,
    const float* __restrict__ W, const float* __restrict__ b,
    float* __restrict__ out, int relu)
{
    __shared__ float As[64][128];   // 32KB, [k][node]
    __shared__ float Ws[64][64];    // 16KB, [k][j]

    const int tid = threadIdx.x;
    const int nb  = blockIdx.x * 128;

    float acc[8][8];
    #pragma unroll
    for (int i = 0; i < 8; i++)
        #pragma unroll
        for (int j = 0; j < 8; j++) acc[i][j] = 0.f;

    const int ng = (tid >> 3) * 8;   // node sub-tile
    const int jg = (tid & 7) * 8;    // col  sub-tile

    #pragma unroll
    for (int c = 0; c < 4; c++) {
        const float4* Ap = (c == 0) ? A0 : (c == 1) ? A1 : (c == 2) ? A2 : A3;

        // Load A tile: thread tid owns node nb+tid, transpose into As[k][node]
        {
            int node = nb + tid;
            const float4* row = Ap + (size_t)node * FEAT4;
            #pragma unroll
            for (int kk = 0; kk < 16; kk++) {
                float4 v = (node < NN) ? __ldg(&row[kk]) : make_float4(0, 0, 0, 0);
                As[kk * 4 + 0][tid] = v.x;
                As[kk * 4 + 1][tid] = v.y;
                As[kk * 4 + 2][tid] = v.z;
                As[kk * 4 + 3][tid] = v.w;
            }
        }
        // Load W chunk [64,64], coalesced float4 copy
        {
            const float4* Wg  = (const float4*)(W + c * 64 * 64);
            float4*       Wsv = (float4*)&Ws[0][0];
            #pragma unroll
            for (int t = 0; t < 8; t++) Wsv[t * 128 + tid] = __ldg(&Wg[t * 128 + tid]);
        }
        __syncthreads();

        #pragma unroll 4
        for (int k = 0; k < 64; k++) {
            float a[8], w[8];
            *(float4*)&a[0] = *(const float4*)&As[k][ng];
            *(float4*)&a[4] = *(const float4*)&As[k][ng + 4];
            *(float4*)&w[0] = *(const float4*)&Ws[k][jg];
            *(float4*)&w[4] = *(const float4*)&Ws[k][jg + 4];
            #pragma unroll
            for (int i = 0; i < 8; i++)
                #pragma unroll
                for (int j = 0; j < 8; j++) acc[i][j] += a[i] * w[j];
        }
        __syncthreads();
    }

    // Epilogue: + bias, optional relu, float4 stores
    float bj[8];
    #pragma unroll
    for (int j = 0; j < 8; j++) bj[j] = b[jg + j];

    #pragma unroll
    for (int i = 0; i < 8; i++) {
        int node = nb + ng + i;
        if (node < NN) {
            float v[8];
            #pragma unroll
            for (int j = 0; j < 8; j++) {
                float t = acc[i][j] + bj[j];
                v[j] = relu ? fmaxf(t, 0.f) : t;
            }
            float4* dst = (float4*)(out + (size_t)node * 64 + jg);
            dst[0] = make_float4(v[0], v[1], v[2], v[3]);
            dst[1] = make_float4(v[4], v[5], v[6], v[7]);
        }
    }
}

// ---------------- classifier: [N,64] @ Wc[64,40] + bc ---------------
__global__ void k_classifier(const float* __restrict__ h,
                             const float* __restrict__ Wc,
                             const float* __restrict__ bc,
                             float* __restrict__ out)
{
    __shared__ float Ws[64 * NCLS];
    __shared__ float bs[NCLS];
    for (int i = threadIdx.x; i < 64 * NCLS; i += blockDim.x) Ws[i] = Wc[i];
    for (int i = threadIdx.x; i < NCLS; i += blockDim.x) bs[i] = bc[i];
    __syncthreads();

    int gid = blockIdx.x * blockDim.x + threadIdx.x;
    if (gid >= NN * NCLS) return;
    int n = gid / NCLS;
    int c = gid % NCLS;
    const float* row = h + (size_t)n * 64;
    float acc = bs[c];
    #pragma unroll
    for (int i = 0; i < 64; i++) acc += row[i] * Ws[i * NCLS + c];
    out[gid] = acc;
}

// ---------------- launch ---------------------------------------------
extern "C" void kernel_launch(void* const* d_in, const int* in_sizes, int n_in,
                              void* d_out, int out_size)
{
    const float* x  = (const float*)d_in[0];
    const void*  ei = d_in[1];
    const float* W1 = (const float*)d_in[2];
    const float* b1 = (const float*)d_in[3];
    const float* W2 = (const float*)d_in[4];
    const float* b2 = (const float*)d_in[5];
    const float* Wc = (const float*)d_in[6];
    const float* bc = (const float*)d_in[7];
    float* out = (float*)d_out;

    void* tmp;
    cudaGetSymbolAddress(&tmp, g_deg);  float*  p_deg  = (float*)tmp;
    cudaGetSymbolAddress(&tmp, g_hop1); float4* p_hop1 = (float4*)tmp;
    cudaGetSymbolAddress(&tmp, g_hop2); float4* p_hop2 = (float4*)tmp;
    cudaGetSymbolAddress(&tmp, g_hop3); float4* p_hop3 = (float4*)tmp;
    cudaGetSymbolAddress(&tmp, g_h1);   float4* p_h1   = (float4*)tmp;
    cudaGetSymbolAddress(&tmp, g_h2);   float4* p_h2   = (float4*)tmp;

    const int EB = (NE + 255) / 256;
    const int SB = (NE * FEAT4 + 255) / 256;
    const int NB = (NN + 255) / 256;
    const int GB = (NN + 127) / 128;
    const int CB = (NN * NCLS + 255) / 256;
    const size_t FB = (size_t)NN * FEAT4 * sizeof(float4);

    // ---- graph preprocessing (recomputed every call: deterministic) ----
    k_detect<<<1, 32>>>((const long long*)ei);
    k_convert<<<EB, 256>>>(ei);
    cudaMemsetAsync(p_deg, 0, NN * sizeof(float));
    k_deg<<<EB, 256>>>();
    k_dinv<<<NB, 256>>>();
    k_norm<<<EB, 256>>>();

    // ---- layer 1: hops of x ----
    cudaMemsetAsync(p_hop1, 0, FB);
    k_spmm<<<SB, 256>>>((const float4*)x, p_hop1);
    cudaMemsetAsync(p_hop2, 0, FB);
    k_spmm<<<SB, 256>>>(p_hop1, p_hop2);
    cudaMemsetAsync(p_hop3, 0, FB);
    k_spmm<<<SB, 256>>>(p_hop2, p_hop3);
    k_gemm<<<GB, 128>>>((const float4*)x, p_hop1, p_hop2, p_hop3,
                        W1, b1, (float*)p_h1, 1);

    // ---- layer 2: hops of h1 ----
    cudaMemsetAsync(p_hop1, 0, FB);
    k_spmm<<<SB, 256>>>(p_h1, p_hop1);
    cudaMemsetAsync(p_hop2, 0, FB);
    k_spmm<<<SB, 256>>>(p_hop1, p_hop2);
    cudaMemsetAsync(p_hop3, 0, FB);
    k_spmm<<<SB, 256>>>(p_hop2, p_hop3);
    k_gemm<<<GB, 128>>>(p_h1, p_hop1, p_hop2, p_hop3,
                        W2, b2, (float*)p_h2, 1);

    // ---- classifier ----
    k_classifier<<<CB, 256>>>((const float*)p_h2, Wc, bc, out);
}

// round 3
// speedup vs baseline: 1.4189x; 1.4189x over previous
#include <cuda_runtime.h>
#include <cuda_bf16.h>

#define NN 100000
#define NE 1200000
#define FEAT4 16           // 64 floats = 16 float4 per node
#define NCLS 40
#define SCAN_NB 391        // ceil(100000/256)

// ---------------- device scratch (no allocs allowed) ----------------
__device__ int    g_src[NE];
__device__ int    g_dst[NE];
__device__ int    g_cnt[NN];          // degree histogram (int)
__device__ int    g_rowptr[NN + 1];
__device__ int    g_fill[NN];
__device__ int    g_bsum[512];        // block partial sums for scan
__device__ float  g_dinv[NN];
__device__ int2   g_csr[NE];          // {src, bitcast(weight)} sorted by dst
__device__ float4 g_hop1[NN * FEAT4];
__device__ float4 g_hop2[NN * FEAT4];
__device__ float4 g_hop3[NN * FEAT4];
__device__ float4 g_h1[NN * FEAT4];
__device__ float4 g_h2[NN * FEAT4];
__device__ int    g_is64;

// ---------------- dtype detection (int64 vs int32 edge_index) -------
__global__ void k_detect(const long long* p) {
    if (blockIdx.x == 0 && threadIdx.x == 0) {
        int ok = 1;
        #pragma unroll 1
        for (int i = 0; i < 64; i++) {
            long long v = p[i * 997];     // stays in src half either way
            if (v < 0 || v >= NN) { ok = 0; break; }
        }
        g_is64 = ok;
    }
}

__global__ void k_convert(const void* edges) {
    int e = blockIdx.x * blockDim.x + threadIdx.x;
    if (e >= NE) return;
    if (g_is64) {
        const long long* p = (const long long*)edges;
        g_src[e] = (int)p[e];
        g_dst[e] = (int)p[e + NE];
    } else {
        const int* p = (const int*)edges;
        g_src[e] = p[e];
        g_dst[e] = p[e + NE];
    }
}

// ---------------- degree histogram + dinv ---------------------------
__global__ void k_hist() {
    int e = blockIdx.x * blockDim.x + threadIdx.x;
    if (e < NE) atomicAdd(&g_cnt[g_dst[e]], 1);
}

__global__ void k_dinv() {
    int n = blockIdx.x * blockDim.x + threadIdx.x;
    if (n < NN) {
        float d = (float)g_cnt[n];
        g_dinv[n] = (d > 0.f) ? rsqrtf(fmaxf(d, 1.f)) : 0.f;
    }
}

// ---------------- exclusive scan of g_cnt -> g_rowptr ---------------
// pass 1: per-block (256 elems) exclusive scan + block sums
__global__ void k_scan1() {
    __shared__ int sh[2][256];
    int tid = threadIdx.x;
    int gid = blockIdx.x * 256 + tid;
    int v = (gid < NN) ? g_cnt[gid] : 0;
    sh[0][tid] = v;
    __syncthreads();
    int cur = 0;
    #pragma unroll
    for (int off = 1; off < 256; off <<= 1) {
        int a = sh[cur][tid];
        if (tid >= off) a += sh[cur][tid - off];
        sh[cur ^ 1][tid] = a;
        cur ^= 1;
        __syncthreads();
    }
    int incl = sh[cur][tid];
    if (gid <= NN) g_rowptr[gid] = incl - v;      // exclusive (offset added later)
    if (tid == 255) g_bsum[blockIdx.x] = incl;
}

// pass 2: single block scans SCAN_NB block sums (exclusive)
__global__ void k_scan2() {
    __shared__ int sh[2][512];
    int tid = threadIdx.x;
    int v = (tid < SCAN_NB) ? g_bsum[tid] : 0;
    sh[0][tid] = v;
    __syncthreads();
    int cur = 0;
    #pragma unroll
    for (int off = 1; off < 512; off <<= 1) {
        int a = sh[cur][tid];
        if (tid >= off) a += sh[cur][tid - off];
        sh[cur ^ 1][tid] = a;
        cur ^= 1;
        __syncthreads();
    }
    if (tid < SCAN_NB) g_bsum[tid] = sh[cur][tid] - v;   // exclusive
}

// pass 3: add block offsets; set rowptr[NN] = NE
__global__ void k_scan3() {
    int gid = blockIdx.x * 256 + threadIdx.x;
    if (gid < NN) g_rowptr[gid] += g_bsum[gid >> 8];
    if (gid == 0) g_rowptr[NN] = NE;
}

// ---------------- CSR fill (weight fused) ---------------------------
__global__ void k_fill() {
    int e = blockIdx.x * blockDim.x + threadIdx.x;
    if (e >= NE) return;
    int s = g_src[e];
    int d = g_dst[e];
    int pos = g_rowptr[d] + atomicAdd(&g_fill[d], 1);
    float w = g_dinv[s] * g_dinv[d];
    g_csr[pos] = make_int2(s, __float_as_int(w));
}

// ---------------- SpMM (CSR pull, no atomics) -----------------------
// 16 threads per node; lane q owns float4 q of the output row.
// Neighbor (src,w) loads are same-address across the 16 lanes -> 1 request.
// Gather feat[src*16+q] is a fully coalesced 256B group read (L2-resident).
__global__ void __launch_bounds__(256) k_spmm_csr(
    const float4* __restrict__ feat, float4* __restrict__ out)
{
    int gid = blockIdx.x * blockDim.x + threadIdx.x;
    if (gid >= NN * 16) return;
    int node = gid >> 4;
    int q    = gid & 15;
    int beg = g_rowptr[node];
    int end = g_rowptr[node + 1];
    float4 acc = make_float4(0.f, 0.f, 0.f, 0.f);
    for (int i = beg; i < end; i++) {
        int2 sw = __ldg(&g_csr[i]);
        float w = __int_as_float(sw.y);
        float4 v = __ldg(&feat[sw.x * FEAT4 + q]);
        acc.x += w * v.x; acc.y += w * v.y;
        acc.z += w * v.z; acc.w += w * v.w;
    }
    out[node * FEAT4 + q] = acc;
}

// ---------------- GEMM: concat(4 x [N,64]) @ W[256,64] + b ----------
__global__ void __launch_bounds__(128) k_gemm(
    const float4* __restrict__ A0, const float4* __restrict__ A1,
    const float4* __restrict__ A2, const float4* __restrict__ A3,
    const float* __restrict__ W, const float* __restrict__ b,
    float* __restrict__ out, int relu)
{
    __shared__ float As[64][128];   // 32KB, [k][node]
    __shared__ float Ws[64][64];    // 16KB, [k][j]

    const int tid = threadIdx.x;
    const int nb  = blockIdx.x * 128;

    float acc[8][8];
    #pragma unroll
    for (int i = 0; i < 8; i++)
        #pragma unroll
        for (int j = 0; j < 8; j++) acc[i][j] = 0.f;

    const int ng = (tid >> 3) * 8;
    const int jg = (tid & 7) * 8;

    #pragma unroll
    for (int c = 0; c < 4; c++) {
        const float4* Ap = (c == 0) ? A0 : (c == 1) ? A1 : (c == 2) ? A2 : A3;
        {
            int node = nb + tid;
            const float4* row = Ap + (size_t)node * FEAT4;
            #pragma unroll
            for (int kk = 0; kk < 16; kk++) {
                float4 v = (node < NN) ? __ldg(&row[kk]) : make_float4(0, 0, 0, 0);
                As[kk * 4 + 0][tid] = v.x;
                As[kk * 4 + 1][tid] = v.y;
                As[kk * 4 + 2][tid] = v.z;
                As[kk * 4 + 3][tid] = v.w;
            }
        }
        {
            const float4* Wg  = (const float4*)(W + c * 64 * 64);
            float4*       Wsv = (float4*)&Ws[0][0];
            #pragma unroll
            for (int t = 0; t < 8; t++) Wsv[t * 128 + tid] = __ldg(&Wg[t * 128 + tid]);
        }
        __syncthreads();

        #pragma unroll 4
        for (int k = 0; k < 64; k++) {
            float a[8], w[8];
            *(float4*)&a[0] = *(const float4*)&As[k][ng];
            *(float4*)&a[4] = *(const float4*)&As[k][ng + 4];
            *(float4*)&w[0] = *(const float4*)&Ws[k][jg];
            *(float4*)&w[4] = *(const float4*)&Ws[k][jg + 4];
            #pragma unroll
            for (int i = 0; i < 8; i++)
                #pragma unroll
                for (int j = 0; j < 8; j++) acc[i][j] += a[i] * w[j];
        }
        __syncthreads();
    }

    float bj[8];
    #pragma unroll
    for (int j = 0; j < 8; j++) bj[j] = b[jg + j];

    #pragma unroll
    for (int i = 0; i < 8; i++) {
        int node = nb + ng + i;
        if (node < NN) {
            float v[8];
            #pragma unroll
            for (int j = 0; j < 8; j++) {
                float t = acc[i][j] + bj[j];
                v[j] = relu ? fmaxf(t, 0.f) : t;
            }
            float4* dst = (float4*)(out + (size_t)node * 64 + jg);
            dst[0] = make_float4(v[0], v[1], v[2], v[3]);
            dst[1] = make_float4(v[4], v[5], v[6], v[7]);
        }
    }
}

// ---------------- classifier: [N,64] @ Wc[64,40] + bc ---------------
__global__ void k_classifier(const float* __restrict__ h,
                             const float* __restrict__ Wc,
                             const float* __restrict__ bc,
                             float* __restrict__ out)
{
    __shared__ float Ws[64 * NCLS];
    __shared__ float bs[NCLS];
    for (int i = threadIdx.x; i < 64 * NCLS; i += blockDim.x) Ws[i] = Wc[i];
    for (int i = threadIdx.x; i < NCLS; i += blockDim.x) bs[i] = bc[i];
    __syncthreads();

    int gid = blockIdx.x * blockDim.x + threadIdx.x;
    if (gid >= NN * NCLS) return;
    int n = gid / NCLS;
    int c = gid % NCLS;
    const float* row = h + (size_t)n * 64;
    float acc = bs[c];
    #pragma unroll
    for (int i = 0; i < 64; i++) acc += row[i] * Ws[i * NCLS + c];
    out[gid] = acc;
}

// ---------------- launch ---------------------------------------------
extern "C" void kernel_launch(void* const* d_in, const int* in_sizes, int n_in,
                              void* d_out, int out_size)
{
    const float* x  = (const float*)d_in[0];
    const void*  ei = d_in[1];
    const float* W1 = (const float*)d_in[2];
    const float* b1 = (const float*)d_in[3];
    const float* W2 = (const float*)d_in[4];
    const float* b2 = (const float*)d_in[5];
    const float* Wc = (const float*)d_in[6];
    const float* bc = (const float*)d_in[7];
    float* out = (float*)d_out;

    void* tmp;
    cudaGetSymbolAddress(&tmp, g_cnt);  int*    p_cnt  = (int*)tmp;
    cudaGetSymbolAddress(&tmp, g_fill); int*    p_fill = (int*)tmp;
    cudaGetSymbolAddress(&tmp, g_hop1); float4* p_hop1 = (float4*)tmp;
    cudaGetSymbolAddress(&tmp, g_hop2); float4* p_hop2 = (float4*)tmp;
    cudaGetSymbolAddress(&tmp, g_hop3); float4* p_hop3 = (float4*)tmp;
    cudaGetSymbolAddress(&tmp, g_h1);   float4* p_h1   = (float4*)tmp;
    cudaGetSymbolAddress(&tmp, g_h2);   float4* p_h2   = (float4*)tmp;

    const int EB = (NE + 255) / 256;
    const int SB = (NN * 16 + 255) / 256;
    const int NB = (NN + 255) / 256;
    const int GB = (NN + 127) / 128;
    const int CB = (NN * NCLS + 255) / 256;

    // ---- CSR build (recomputed every call: deterministic work) ----
    k_detect<<<1, 32>>>((const long long*)ei);
    k_convert<<<EB, 256>>>(ei);
    cudaMemsetAsync(p_cnt, 0, NN * sizeof(int));
    cudaMemsetAsync(p_fill, 0, NN * sizeof(int));
    k_hist<<<EB, 256>>>();
    k_dinv<<<NB, 256>>>();
    k_scan1<<<SCAN_NB, 256>>>();
    k_scan2<<<1, 512>>>();
    k_scan3<<<SCAN_NB, 256>>>();
    k_fill<<<EB, 256>>>();

    // ---- layer 1: hops of x ----
    k_spmm_csr<<<SB, 256>>>((const float4*)x, p_hop1);
    k_spmm_csr<<<SB, 256>>>(p_hop1, p_hop2);
    k_spmm_csr<<<SB, 256>>>(p_hop2, p_hop3);
    k_gemm<<<GB, 128>>>((const float4*)x, p_hop1, p_hop2, p_hop3,
                        W1, b1, (float*)p_h1, 1);

    // ---- layer 2: hops of h1 ----
    k_spmm_csr<<<SB, 256>>>(p_h1, p_hop1);
    k_spmm_csr<<<SB, 256>>>(p_hop1, p_hop2);
    k_spmm_csr<<<SB, 256>>>(p_hop2, p_hop3);
    k_gemm<<<GB, 128>>>(p_h1, p_hop1, p_hop2, p_hop3,
                        W2, b2, (float*)p_h2, 1);

    // ---- classifier ----
    k_classifier<<<CB, 256>>>((const float*)p_h2, Wc, bc, out);
}

// round 5
// speedup vs baseline: 1.5132x; 1.0664x over previous
#include <cuda_runtime.h>
#include <cuda_bf16.h>
#include <cstdint>

#define NN 100000
#define NE 1200000
#define FEAT4 16           // 64 floats = 16 float4 per node
#define NCLS 40
#define SCAN_NB 391        // ceil(100000/256)

// ---------------- device scratch (no allocs allowed) ----------------
__device__ int    g_src[NE];
__device__ int    g_dst[NE];
__device__ int    g_cnt[NN];
__device__ int    g_rowptr[NN + 1];
__device__ int    g_fill[NN];
__device__ int    g_bsum[512];
__device__ float  g_dinv[NN];
__device__ int2   g_csr[NE];          // {src, bitcast(weight)} grouped by dst
__device__ float4 g_hop1[NN * FEAT4];
__device__ float4 g_hop2[NN * FEAT4];
__device__ float4 g_hop3[NN * FEAT4];
__device__ float4 g_h1[NN * FEAT4];
__device__ float4 g_h2[NN * FEAT4];
__device__ int    g_is64;

// ---------------- dtype detection (int64 vs int32 edge_index) -------
__global__ void k_detect(const long long* p) {
    if (blockIdx.x == 0 && threadIdx.x == 0) {
        int ok = 1;
        #pragma unroll 1
        for (int i = 0; i < 64; i++) {
            long long v = p[i * 997];
            if (v < 0 || v >= NN) { ok = 0; break; }
        }
        g_is64 = ok;
    }
}

__global__ void k_convert(const void* edges) {
    int e = blockIdx.x * blockDim.x + threadIdx.x;
    if (e >= NE) return;
    if (g_is64) {
        const long long* p = (const long long*)edges;
        g_src[e] = (int)p[e];
        g_dst[e] = (int)p[e + NE];
    } else {
        const int* p = (const int*)edges;
        g_src[e] = p[e];
        g_dst[e] = p[e + NE];
    }
}

// ---------------- degree histogram + dinv ---------------------------
__global__ void k_hist() {
    int e = blockIdx.x * blockDim.x + threadIdx.x;
    if (e < NE) atomicAdd(&g_cnt[g_dst[e]], 1);
}

__global__ void k_dinv() {
    int n = blockIdx.x * blockDim.x + threadIdx.x;
    if (n < NN) {
        float d = (float)g_cnt[n];
        g_dinv[n] = (d > 0.f) ? rsqrtf(fmaxf(d, 1.f)) : 0.f;
    }
}

// ---------------- exclusive scan of g_cnt -> g_rowptr ---------------
__global__ void k_scan1() {
    __shared__ int sh[2][256];
    int tid = threadIdx.x;
    int gid = blockIdx.x * 256 + tid;
    int v = (gid < NN) ? g_cnt[gid] : 0;
    sh[0][tid] = v;
    __syncthreads();
    int cur = 0;
    #pragma unroll
    for (int off = 1; off < 256; off <<= 1) {
        int a = sh[cur][tid];
        if (tid >= off) a += sh[cur][tid - off];
        sh[cur ^ 1][tid] = a;
        cur ^= 1;
        __syncthreads();
    }
    int incl = sh[cur][tid];
    if (gid <= NN) g_rowptr[gid] = incl - v;
    if (tid == 255) g_bsum[blockIdx.x] = incl;
}

__global__ void k_scan2() {
    __shared__ int sh[2][512];
    int tid = threadIdx.x;
    int v = (tid < SCAN_NB) ? g_bsum[tid] : 0;
    sh[0][tid] = v;
    __syncthreads();
    int cur = 0;
    #pragma unroll
    for (int off = 1; off < 512; off <<= 1) {
        int a = sh[cur][tid];
        if (tid >= off) a += sh[cur][tid - off];
        sh[cur ^ 1][tid] = a;
        cur ^= 1;
        __syncthreads();
    }
    if (tid < SCAN_NB) g_bsum[tid] = sh[cur][tid] - v;
}

__global__ void k_scan3() {
    int gid = blockIdx.x * 256 + threadIdx.x;
    if (gid < NN) g_rowptr[gid] += g_bsum[gid >> 8];
    if (gid == 0) g_rowptr[NN] = NE;
}

// ---------------- CSR fill (weight fused) ---------------------------
__global__ void k_fill() {
    int e = blockIdx.x * blockDim.x + threadIdx.x;
    if (e >= NE) return;
    int s = g_src[e];
    int d = g_dst[e];
    int pos = g_rowptr[d] + atomicAdd(&g_fill[d], 1);
    float w = g_dinv[s] * g_dinv[d];
    g_csr[pos] = make_int2(s, __float_as_int(w));
}

// ---------------- SpMM (CSR pull, no atomics) -----------------------
__global__ void __launch_bounds__(256) k_spmm_csr(
    const float4* __restrict__ feat, float4* __restrict__ out)
{
    int gid = blockIdx.x * blockDim.x + threadIdx.x;
    if (gid >= NN * 16) return;
    int node = gid >> 4;
    int q    = gid & 15;
    int beg = g_rowptr[node];
    int end = g_rowptr[node + 1];
    float4 acc = make_float4(0.f, 0.f, 0.f, 0.f);
    for (int i = beg; i < end; i++) {
        int2 sw = __ldg(&g_csr[i]);
        float w = __int_as_float(sw.y);
        float4 v = __ldg(&feat[sw.x * FEAT4 + q]);
        acc.x += w * v.x; acc.y += w * v.y;
        acc.z += w * v.z; acc.w += w * v.w;
    }
    out[node * FEAT4 + q] = acc;
}

// ====================================================================
// HMMA tf32 split-3 GEMM: out[128-tile,64] = concat(hops)[*,256] @ W + b
// mma.sync.aligned.m16n8k8 (non-arch-specific; compiles for compute_103)
// ====================================================================
#define APITCH 136   // bank = (136k + m)%32 = (8k + m)%32 -> frag loads conflict-free
#define WPITCH 72    // bank = (72k + n)%32  = (8k + n)%32 -> conflict-free

__device__ __forceinline__ uint32_t tf32_hi(float x) {
    float r;
    asm("cvt.rna.tf32.f32 %0, %1;" : "=f"(r) : "f"(x));
    return __float_as_uint(r);
}

__device__ __forceinline__ void mma_t(float* c, const uint32_t* a,
                                      uint32_t b0, uint32_t b1) {
    asm volatile(
        "mma.sync.aligned.m16n8k8.row.col.f32.tf32.tf32.f32 "
        "{%0,%1,%2,%3}, {%4,%5,%6,%7}, {%8,%9}, {%0,%1,%2,%3};"
        : "+f"(c[0]), "+f"(c[1]), "+f"(c[2]), "+f"(c[3])
        : "r"(a[0]), "r"(a[1]), "r"(a[2]), "r"(a[3]), "r"(b0), "r"(b1));
}

__global__ void __launch_bounds__(128) k_gemm_mma(
    const float4* __restrict__ A0, const float4* __restrict__ A1,
    const float4* __restrict__ A2, const float4* __restrict__ A3,
    const float* __restrict__ W, const float* __restrict__ b,
    float* __restrict__ out, int relu)
{
    __shared__ float As[64][APITCH];   // [k][m], fp32
    __shared__ float Ws[64][WPITCH];   // [k][n], fp32

    const int tid  = threadIdx.x;
    const int lane = tid & 31;
    const int w    = tid >> 5;     // warp 0..3 -> rows w*32..w*32+31
    const int g    = lane >> 2;    // group 0..7
    const int tig  = lane & 3;     // 0..3
    const int nb   = blockIdx.x * 128;

    float acc[2][8][4];
    #pragma unroll
    for (int mt = 0; mt < 2; mt++)
        #pragma unroll
        for (int nt = 0; nt < 8; nt++)
            #pragma unroll
            for (int i = 0; i < 4; i++) acc[mt][nt][i] = 0.f;

    #pragma unroll 1
    for (int c = 0; c < 4; c++) {
        const float4* Ap = (c == 0) ? A0 : (c == 1) ? A1 : (c == 2) ? A2 : A3;
        if (c) __syncthreads();

        // ---- fill A tile: thread = node column ----
        {
            int node = nb + tid;
            const float4* row = Ap + (size_t)node * FEAT4;
            #pragma unroll
            for (int j = 0; j < 16; j++) {
                float4 v = (node < NN) ? __ldg(&row[j]) : make_float4(0, 0, 0, 0);
                As[j * 4 + 0][tid] = v.x;
                As[j * 4 + 1][tid] = v.y;
                As[j * 4 + 2][tid] = v.z;
                As[j * 4 + 3][tid] = v.w;
            }
        }
        // ---- fill W tile (64x64 of [256,64] row-major) ----
        #pragma unroll
        for (int t = 0; t < 32; t++) {
            int idx = t * 128 + tid;
            int k = idx >> 6, n = idx & 63;
            Ws[k][n] = __ldg(&W[(c * 64 + k) * 64 + n]);
        }
        __syncthreads();

        #pragma unroll
        for (int ks = 0; ks < 8; ks++) {
            int k0 = ks * 8;
            // A fragments (hi/lo) for both m-tiles
            uint32_t ahi[2][4], alo[2][4];
            #pragma unroll
            for (int mt = 0; mt < 2; mt++) {
                int mb = w * 32 + mt * 16;
                float f0 = As[k0 + tig][mb + g];
                float f1 = As[k0 + tig][mb + 8 + g];
                float f2 = As[k0 + 4 + tig][mb + g];
                float f3 = As[k0 + 4 + tig][mb + 8 + g];
                ahi[mt][0] = tf32_hi(f0); alo[mt][0] = tf32_hi(f0 - __uint_as_float(ahi[mt][0]));
                ahi[mt][1] = tf32_hi(f1); alo[mt][1] = tf32_hi(f1 - __uint_as_float(ahi[mt][1]));
                ahi[mt][2] = tf32_hi(f2); alo[mt][2] = tf32_hi(f2 - __uint_as_float(ahi[mt][2]));
                ahi[mt][3] = tf32_hi(f3); alo[mt][3] = tf32_hi(f3 - __uint_as_float(ahi[mt][3]));
            }
            #pragma unroll
            for (int nt = 0; nt < 8; nt++) {
                float w0 = Ws[k0 + tig][nt * 8 + g];
                float w1 = Ws[k0 + 4 + tig][nt * 8 + g];
                uint32_t bhi0 = tf32_hi(w0), blo0 = tf32_hi(w0 - __uint_as_float(bhi0));
                uint32_t bhi1 = tf32_hi(w1), blo1 = tf32_hi(w1 - __uint_as_float(bhi1));
                #pragma unroll
                for (int mt = 0; mt < 2; mt++) {
                    mma_t(acc[mt][nt], ahi[mt], bhi0, bhi1);
                    mma_t(acc[mt][nt], ahi[mt], blo0, blo1);
                    mma_t(acc[mt][nt], alo[mt], bhi0, bhi1);
                }
            }
        }
    }

    // ---- epilogue: c0,c1 at (row g, col 2tig), c2,c3 at (row g+8) ----
    #pragma unroll
    for (int mt = 0; mt < 2; mt++) {
        int row0 = nb + w * 32 + mt * 16 + g;
        int row1 = row0 + 8;
        #pragma unroll
        for (int nt = 0; nt < 8; nt++) {
            int col = nt * 8 + 2 * tig;
            float b0 = __ldg(&b[col]), b1 = __ldg(&b[col + 1]);
            float v0 = acc[mt][nt][0] + b0, v1 = acc[mt][nt][1] + b1;
            float v2 = acc[mt][nt][2] + b0, v3 = acc[mt][nt][3] + b1;
            if (relu) {
                v0 = fmaxf(v0, 0.f); v1 = fmaxf(v1, 0.f);
                v2 = fmaxf(v2, 0.f); v3 = fmaxf(v3, 0.f);
            }
            if (row0 < NN) *(float2*)(out + (size_t)row0 * 64 + col) = make_float2(v0, v1);
            if (row1 < NN) *(float2*)(out + (size_t)row1 * 64 + col) = make_float2(v2, v3);
        }
    }
}

// ---------------- classifier: [N,64] @ Wc[64,40] + bc ---------------
__global__ void k_classifier(const float* __restrict__ h,
                             const float* __restrict__ Wc,
                             const float* __restrict__ bc,
                             float* __restrict__ out)
{
    __shared__ float Ws[64 * NCLS];
    __shared__ float bs[NCLS];
    for (int i = threadIdx.x; i < 64 * NCLS; i += blockDim.x) Ws[i] = Wc[i];
    for (int i = threadIdx.x; i < NCLS; i += blockDim.x) bs[i] = bc[i];
    __syncthreads();

    int gid = blockIdx.x * blockDim.x + threadIdx.x;
    if (gid >= NN * NCLS) return;
    int n = gid / NCLS;
    int c = gid % NCLS;
    const float* row = h + (size_t)n * 64;
    float acc = bs[c];
    #pragma unroll
    for (int i = 0; i < 64; i++) acc += row[i] * Ws[i * NCLS + c];
    out[gid] = acc;
}

// ---------------- launch ---------------------------------------------
extern "C" void kernel_launch(void* const* d_in, const int* in_sizes, int n_in,
                              void* d_out, int out_size)
{
    const float* x  = (const float*)d_in[0];
    const void*  ei = d_in[1];
    const float* W1 = (const float*)d_in[2];
    const float* b1 = (const float*)d_in[3];
    const float* W2 = (const float*)d_in[4];
    const float* b2 = (const float*)d_in[5];
    const float* Wc = (const float*)d_in[6];
    const float* bc = (const float*)d_in[7];
    float* out = (float*)d_out;

    void* tmp;
    cudaGetSymbolAddress(&tmp, g_cnt);  int*    p_cnt  = (int*)tmp;
    cudaGetSymbolAddress(&tmp, g_fill); int*    p_fill = (int*)tmp;
    cudaGetSymbolAddress(&tmp, g_hop1); float4* p_hop1 = (float4*)tmp;
    cudaGetSymbolAddress(&tmp, g_hop2); float4* p_hop2 = (float4*)tmp;
    cudaGetSymbolAddress(&tmp, g_hop3); float4* p_hop3 = (float4*)tmp;
    cudaGetSymbolAddress(&tmp, g_h1);   float4* p_h1   = (float4*)tmp;
    cudaGetSymbolAddress(&tmp, g_h2);   float4* p_h2   = (float4*)tmp;

    const int EB = (NE + 255) / 256;
    const int SB = (NN * 16 + 255) / 256;
    const int NB = (NN + 255) / 256;
    const int GB = (NN + 127) / 128;
    const int CB = (NN * NCLS + 255) / 256;

    // ---- CSR build ----
    k_detect<<<1, 32>>>((const long long*)ei);
    k_convert<<<EB, 256>>>(ei);
    cudaMemsetAsync(p_cnt, 0, NN * sizeof(int));
    cudaMemsetAsync(p_fill, 0, NN * sizeof(int));
    k_hist<<<EB, 256>>>();
    k_dinv<<<NB, 256>>>();
    k_scan1<<<SCAN_NB, 256>>>();
    k_scan2<<<1, 512>>>();
    k_scan3<<<SCAN_NB, 256>>>();
    k_fill<<<EB, 256>>>();

    // ---- layer 1 ----
    k_spmm_csr<<<SB, 256>>>((const float4*)x, p_hop1);
    k_spmm_csr<<<SB, 256>>>(p_hop1, p_hop2);
    k_spmm_csr<<<SB, 256>>>(p_hop2, p_hop3);
    k_gemm_mma<<<GB, 128>>>((const float4*)x, p_hop1, p_hop2, p_hop3,
                            W1, b1, (float*)p_h1, 1);

    // ---- layer 2 ----
    k_spmm_csr<<<SB, 256>>>(p_h1, p_hop1);
    k_spmm_csr<<<SB, 256>>>(p_hop1, p_hop2);
    k_spmm_csr<<<SB, 256>>>(p_hop2, p_hop3);
    k_gemm_mma<<<GB, 128>>>(p_h1, p_hop1, p_hop2, p_hop3,
                            W2, b2, (float*)p_h2, 1);

    // ---- classifier ----
    k_classifier<<<CB, 256>>>((const float*)p_h2, Wc, bc, out);
}